// round 4
// baseline (speedup 1.0000x reference)
#include <cuda_runtime.h>
#include <cuda_bf16.h>
#include <math.h>

#define MAXN 10000
#define MAXE 320000

// ---------------- scratch (device globals; no runtime alloc) ----------------
__device__ float g_s  [MAXN*32];
__device__ float g_v  [MAXN*96];    // (N,3,32)
__device__ float g_scs[MAXN*32];
__device__ float g_scv[MAXN*96];
__device__ float g_xs [MAXN*32];
__device__ float g_xv [MAXN*96];
__device__ float g_aggs[MAXN*64];
__device__ float g_aggv[MAXN*192];
// CSR (by dst) + permuted edge data
__device__ int   g_deg   [MAXN];
__device__ int   g_cursor[MAXN];
__device__ int   g_rowstart[MAXN+1];
__device__ int   g_slot  [MAXE];
__device__ int   g_srcP  [MAXE];
__device__ float g_embP  [MAXE*10];
__device__ float g_YP    [MAXE*3];
// per-edge radial weights, bf16, double-buffered per layer
__device__ __nv_bfloat16 g_wb0[MAXE*128];
__device__ __nv_bfloat16 g_wb1[MAXE*128];

// ---------------- constants ----------------
#define SQRT3F   1.7320508075688772f
#define ISQRT3F  0.5773502691896258f
#define INV_NB   0.17677669529663687f
#define NORM128  0.08838834764831845f
#define NORM256  0.0625f
#define INVS10   0.3162277660168379f
#define C_S      0.3826834323650898f
#define C_X      0.9238795325112867f
#define PI_F     3.14159265358979f
#define WG_TE    128

// ---------------- packed f32x2 helpers ----------------
__device__ __forceinline__ unsigned long long pack2(float lo, float hi) {
    unsigned long long r;
    asm("mov.b64 %0, {%1, %2};" : "=l"(r) : "f"(lo), "f"(hi));
    return r;
}
__device__ __forceinline__ void ffma2(unsigned long long& acc,
                                      unsigned long long a, unsigned long long b) {
    asm("fma.rn.f32x2 %0, %1, %2, %0;" : "+l"(acc) : "l"(a), "l"(b));
}
__device__ __forceinline__ void mul2(unsigned long long& v, unsigned long long s) {
    asm("mul.rn.f32x2 %0, %0, %1;" : "+l"(v) : "l"(s));
}
__device__ __forceinline__ float2 unpack2(unsigned long long v) {
    float2 f;
    asm("mov.b64 {%0, %1}, %2;" : "=f"(f.x), "=f"(f.y) : "l"(v));
    return f;
}
// lo of result = a, hi = b
__device__ __forceinline__ unsigned int bf16x2_of(float a, float b) {
    unsigned int r;
    asm("cvt.rn.bf16x2.f32 %0, %1, %2;" : "=r"(r) : "f"(b), "f"(a));
    return r;
}

// ---------------- CSR build ----------------
__global__ void k_zero_deg(int N) {
    int i = blockIdx.x * blockDim.x + threadIdx.x;
    if (i < N) g_deg[i] = 0;
}
__global__ void k_hist(const int* __restrict__ edst, int E) {
    int e = blockIdx.x * blockDim.x + threadIdx.x;
    if (e < E) atomicAdd(&g_deg[edst[e]], 1);
}
#define SCAN_T 1024
__global__ void k_scan(int N) {
    __shared__ int sums[SCAN_T];
    int t = threadIdx.x;
    int IT = (N + SCAN_T - 1) / SCAN_T;
    int lo = t * IT, hi = lo + IT; if (hi > N) hi = N; if (lo > N) lo = N;
    int s = 0;
    for (int i = lo; i < hi; i++) s += g_deg[i];
    sums[t] = s;
    __syncthreads();
    for (int off = 1; off < SCAN_T; off <<= 1) {
        int v = (t >= off) ? sums[t - off] : 0;
        __syncthreads();
        sums[t] += v;
        __syncthreads();
    }
    int run = (t == 0) ? 0 : sums[t - 1];
    for (int i = lo; i < hi; i++) {
        g_rowstart[i] = run;
        g_cursor[i]   = run;
        run += g_deg[i];
    }
    if (hi == N) g_rowstart[N] = run;
}
__global__ void k_fill(const int* __restrict__ esrc, const int* __restrict__ edst, int E) {
    int e = blockIdx.x * blockDim.x + threadIdx.x;
    if (e >= E) return;
    int pos = atomicAdd(&g_cursor[edst[e]], 1);
    g_slot[e] = pos;
    g_srcP[pos] = esrc[e];
}

// ---------------- precompute ----------------
__global__ void k_pre_edges(const float* __restrict__ evec, int E) {
    int e = blockIdx.x * blockDim.x + threadIdx.x;
    if (e >= E) return;
    int p = g_slot[e];
    float vx = evec[e*3+0], vy = evec[e*3+1], vz = evec[e*3+2];
    float len = sqrtf(vx*vx + vy*vy + vz*vz);
    float inv = 1.0f / (len + 1e-9f);
    g_YP[p*3+0] = SQRT3F * vx * inv;
    g_YP[p*3+1] = SQRT3F * vy * inv;
    g_YP[p*3+2] = SQRT3F * vz * inv;
    float u = 0.5f*len - 2.0f;
    float cut;
    if (u > 0.0f)       cut = 0.0f;
    else if (u < -1.0f) cut = 1.0f;
    else                cut = (1.0f - __cosf(PI_F * u)) * 0.5f;
#pragma unroll
    for (int b = 0; b < 10; b++) {
        float c = (4.0f/9.0f) * (float)b;
        float d = (len - c) * 2.5f;
        g_embP[p*10+b] = __expf(-d*d) * cut;
    }
}

__global__ void k_pre_nodes(const float* __restrict__ x, int N) {
    int i = blockIdx.x * blockDim.x + threadIdx.x;
    if (i >= N*32) return;
    int n = i >> 5, u = i & 31;
    g_s[i] = x[n*128 + u];
    g_v[n*96 +      u] = x[n*128 + 32 + u*3 + 0];
    g_v[n*96 + 32 + u] = x[n*128 + 32 + u*3 + 1];
    g_v[n*96 + 64 + u] = x[n*128 + 32 + u*3 + 2];
}

// ================= device bodies (for fused launches) ======================

// --- wgemm body: needs 73728 B of dynamic smem, 256 threads ---
__device__ void wgemm_dev(float* sm, const float* __restrict__ Wfc1,
                          const float* __restrict__ Wfc2,
                          __nv_bfloat16* __restrict__ wout, int E, int bid) {
    float* shW1  = sm;            // 640
    float* shW2  = sm + 640;      // 8192
    float* shEmb = sm + 8832;     // 1280
    float* shH   = sm + 10112;    // 8320 (stride 65)
    int tid = threadIdx.x;
    int eg0 = bid * WG_TE;
    int nE = E - eg0; if (nE > WG_TE) nE = WG_TE;

    for (int i = tid; i < 640; i += 256) shW1[i] = Wfc1[i];
    for (int i = tid; i < 8192; i += 256) shW2[i] = Wfc2[i];
    for (int i = tid; i < WG_TE*10; i += 256) shEmb[i] = (i < nE*10) ? g_embP[eg0*10 + i] : 0.f;
    __syncthreads();

    for (int idx = tid; idx < WG_TE*64; idx += 256) {
        int e = idx >> 6, k = idx & 63;
        float acc = 0.f;
#pragma unroll
        for (int b = 0; b < 10; b++) acc += shEmb[e*10+b] * shW1[b*64+k];
        acc *= INVS10;
        shH[e*65 + k] = acc / (1.0f + __expf(-acc));
    }
    __syncthreads();

    int c0 = (tid & 15) * 8;
    int e0 = (tid >> 4) * 8;
    unsigned long long acc[8][4];
#pragma unroll
    for (int e = 0; e < 8; e++)
#pragma unroll
        for (int c = 0; c < 4; c++) acc[e][c] = 0ull;

#pragma unroll 4
    for (int k = 0; k < 64; k++) {
        const unsigned long long* Wrow = (const unsigned long long*)&shW2[k*128 + c0];
        unsigned long long w0 = Wrow[0], w1 = Wrow[1], w2 = Wrow[2], w3 = Wrow[3];
#pragma unroll
        for (int e = 0; e < 8; e++) {
            float hv = shH[(e0+e)*65 + k];
            unsigned long long hp = pack2(hv, hv);
            ffma2(acc[e][0], hp, w0);
            ffma2(acc[e][1], hp, w1);
            ffma2(acc[e][2], hp, w2);
            ffma2(acc[e][3], hp, w3);
        }
    }

    unsigned long long sc = pack2(0.125f, 0.125f);
#pragma unroll
    for (int e = 0; e < 8; e++) {
        int ge = eg0 + e0 + e;
        if (ge >= E) break;
        mul2(acc[e][0], sc); mul2(acc[e][1], sc);
        mul2(acc[e][2], sc); mul2(acc[e][3], sc);
        float2 f0 = unpack2(acc[e][0]);
        float2 f1 = unpack2(acc[e][1]);
        float2 f2 = unpack2(acc[e][2]);
        float2 f3 = unpack2(acc[e][3]);
        uint4 pk;
        pk.x = bf16x2_of(f0.x, f0.y);
        pk.y = bf16x2_of(f1.x, f1.y);
        pk.z = bf16x2_of(f2.x, f2.y);
        pk.w = bf16x2_of(f3.x, f3.y);
        *(uint4*)&wout[ge*128 + c0] = pk;
    }
}

// --- fctp1 body: uses 64 KB of dynamic smem, 256 threads, grid-stride ---
__device__ void fctp1_dev(float* sm, const float* __restrict__ attr,
                          const float* __restrict__ W0, const float* __restrict__ W1,
                          const float* __restrict__ L0, const float* __restrict__ L1,
                          int N, int relBid, int nBlocks) {
    float* s0 = sm;          float* s1 = sm + 4096;
    float* s2 = sm + 8192;   float* s3 = sm + 12288;
    for (int i = threadIdx.x; i < 4096; i += 256) {
        s0[i] = W0[i]; s1[i] = W1[i]; s2[i] = L0[i]; s3[i] = L1[i];
    }
    __syncthreads();
    int lane = threadIdx.x & 31;
    int wid  = relBid * 8 + (threadIdx.x >> 5);
    int wstr = nBlocks * 8;
    for (int n = wid; n < N; n += wstr) {
        float sl = g_s[n*32 + lane];
        float v0 = g_v[n*96 + lane];
        float v1 = g_v[n*96 + 32 + lane];
        float v2 = g_v[n*96 + 64 + lane];
        float at[4] = {attr[n*4+0], attr[n*4+1], attr[n*4+2], attr[n*4+3]};
        float scs=0.f, xs=0.f, scv0=0.f, scv1=0.f, scv2=0.f, xv0=0.f, xv1=0.f, xv2=0.f;
        for (int u = 0; u < 32; u++) {
            float su  = __shfl_sync(0xffffffffu, sl, u);
            float vu0 = __shfl_sync(0xffffffffu, v0, u);
            float vu1 = __shfl_sync(0xffffffffu, v1, u);
            float vu2 = __shfl_sync(0xffffffffu, v2, u);
            int base = u*128 + lane;
#pragma unroll
            for (int a = 0; a < 4; a++) {
                float ca = at[a];
                int wi = base + a*32;
                float cs = su * ca;
                scs += cs * s0[wi];
                xs  += cs * s2[wi];
                float w1 = s1[wi], w2 = s3[wi];
                float c0 = vu0*ca, c1 = vu1*ca, c2 = vu2*ca;
                scv0 += c0*w1; scv1 += c1*w1; scv2 += c2*w1;
                xv0  += c0*w2; xv1  += c1*w2; xv2  += c2*w2;
            }
        }
        g_scs[n*32+lane] = scs*NORM128;
        g_xs [n*32+lane] = xs *NORM128;
        g_scv[n*96+lane]      = scv0*NORM128;
        g_scv[n*96+32+lane]   = scv1*NORM128;
        g_scv[n*96+64+lane]   = scv2*NORM128;
        g_xv [n*96+lane]      = xv0*NORM128;
        g_xv [n*96+32+lane]   = xv1*NORM128;
        g_xv [n*96+64+lane]   = xv2*NORM128;
    }
}

// --- gather body: one node per 128 threads ---
__device__ void gather_node(const __nv_bfloat16* __restrict__ win, int n, int sub) {
    int k = sub >> 5, u = sub & 31;
    int t0 = g_rowstart[n];
    int t1 = g_rowstart[n+1];
    float a0 = 0.f, a1 = 0.f, a2 = 0.f;

    if (k == 0) {
        int e = t0;
        for (; e + 4 <= t1; e += 4) {
            int s0 = g_srcP[e], s1 = g_srcP[e+1], s2 = g_srcP[e+2], s3 = g_srcP[e+3];
            float w0 = __bfloat162float(win[(e+0)*128 + sub]);
            float w1 = __bfloat162float(win[(e+1)*128 + sub]);
            float w2 = __bfloat162float(win[(e+2)*128 + sub]);
            float w3 = __bfloat162float(win[(e+3)*128 + sub]);
            a0 += w0 * g_xs[s0*32 + u];
            a1 += w1 * g_xs[s1*32 + u];
            a0 += w2 * g_xs[s2*32 + u];
            a1 += w3 * g_xs[s3*32 + u];
        }
        for (; e < t1; e++)
            a0 += __bfloat162float(win[e*128 + sub]) * g_xs[g_srcP[e]*32 + u];
        g_aggs[n*64 + u] = (a0 + a1) * INV_NB;
    } else if (k == 1) {
        int e = t0;
        for (; e + 2 <= t1; e += 2) {
            int s0 = g_srcP[e], s1 = g_srcP[e+1];
            float w0 = __bfloat162float(win[(e+0)*128 + sub]);
            float w1 = __bfloat162float(win[(e+1)*128 + sub]);
            float d0 = g_YP[e*3+0]*g_xv[s0*96+u] + g_YP[e*3+1]*g_xv[s0*96+32+u]
                     + g_YP[e*3+2]*g_xv[s0*96+64+u];
            float d1 = g_YP[e*3+3]*g_xv[s1*96+u] + g_YP[e*3+4]*g_xv[s1*96+32+u]
                     + g_YP[e*3+5]*g_xv[s1*96+64+u];
            a0 += w0 * d0;
            a1 += w1 * d1;
        }
        for (; e < t1; e++) {
            int s0 = g_srcP[e];
            float w = __bfloat162float(win[e*128 + sub]);
            a0 += w * (g_YP[e*3+0]*g_xv[s0*96+u] + g_YP[e*3+1]*g_xv[s0*96+32+u]
                     + g_YP[e*3+2]*g_xv[s0*96+64+u]);
        }
        g_aggs[n*64 + 32 + u] = (a0 + a1) * ISQRT3F * INV_NB;
    } else if (k == 2) {
        for (int e = t0; e < t1; e++) {
            float m = __bfloat162float(win[e*128 + sub]) * g_xs[g_srcP[e]*32 + u];
            a0 += m * g_YP[e*3+0];
            a1 += m * g_YP[e*3+1];
            a2 += m * g_YP[e*3+2];
        }
        g_aggv[n*192 +       u] = a0 * INV_NB;
        g_aggv[n*192 +  64 + u] = a1 * INV_NB;
        g_aggv[n*192 + 128 + u] = a2 * INV_NB;
    } else {
        for (int e = t0; e < t1; e++) {
            float w = __bfloat162float(win[e*128 + sub]);
            int src = g_srcP[e];
            a0 += w * g_xv[src*96 + u];
            a1 += w * g_xv[src*96 + 32 + u];
            a2 += w * g_xv[src*96 + 64 + u];
        }
        g_aggv[n*192 +  32 + u] = a0 * INV_NB;
        g_aggv[n*192 +  96 + u] = a1 * INV_NB;
        g_aggv[n*192 + 160 + u] = a2 * INV_NB;
    }
}

// ================= fused launches ======================

// A: wgemm(layer0) || fctp1(layer0)
__global__ void __launch_bounds__(256)
k_fusedA(const float* __restrict__ attr,
         const float* __restrict__ W0, const float* __restrict__ W1,
         const float* __restrict__ L0, const float* __restrict__ L1,
         const float* __restrict__ Wfc1, const float* __restrict__ Wfc2,
         int N, int E, int nWG, int nFC) {
    extern __shared__ float sm[];
    if ((int)blockIdx.x < nWG) wgemm_dev(sm, Wfc1, Wfc2, g_wb0, E, blockIdx.x);
    else fctp1_dev(sm, attr, W0, W1, L0, L1, N, blockIdx.x - nWG, nFC);
}

// B: wgemm(layer1) || gather(layer0)
__global__ void __launch_bounds__(256)
k_fusedB(const float* __restrict__ Wfc1, const float* __restrict__ Wfc2,
         int N, int E, int nWG) {
    extern __shared__ float sm[];
    if ((int)blockIdx.x < nWG) {
        wgemm_dev(sm, Wfc1, Wfc2, g_wb1, E, blockIdx.x);
    } else {
        int gb = blockIdx.x - nWG;
        int n = gb*2 + (threadIdx.x >> 7);
        if (n < N) gather_node(g_wb0, n, threadIdx.x & 127);
    }
}

// standalone gather (layer1)
__global__ void __launch_bounds__(256)
k_gather(int N) {
    int n = blockIdx.x*2 + (threadIdx.x >> 7);
    if (n < N) gather_node(g_wb1, n, threadIdx.x & 127);
}

// standalone fctp1 (layer1)
__global__ void __launch_bounds__(256)
k_fctp1(const float* __restrict__ attr,
        const float* __restrict__ W0, const float* __restrict__ W1,
        const float* __restrict__ L0, const float* __restrict__ L1, int N) {
    extern __shared__ float sm[];
    fctp1_dev(sm, attr, W0, W1, L0, L1, N, blockIdx.x, gridDim.x);
}

// ---------------- fctp #2 + gated state update ----------------
__global__ void k_fctp2(const float* __restrict__ attr,
                        const float* __restrict__ W20, const float* __restrict__ W21,
                        int N) {
    extern __shared__ float sm[];
    float* s0 = sm; float* s1 = sm + 8192;
    for (int i = threadIdx.x; i < 8192; i += blockDim.x) { s0[i] = W20[i]; s1[i] = W21[i]; }
    __syncthreads();
    int lane = threadIdx.x & 31;
    int wid  = blockIdx.x * (blockDim.x >> 5) + (threadIdx.x >> 5);
    int wstr = gridDim.x * (blockDim.x >> 5);
    for (int n = wid; n < N; n += wstr) {
        float sa = g_aggs[n*64 + lane],       sb = g_aggs[n*64 + 32 + lane];
        float va0 = g_aggv[n*192 + lane],       vb0 = g_aggv[n*192 + 32 + lane];
        float va1 = g_aggv[n*192 + 64 + lane],  vb1 = g_aggv[n*192 + 96 + lane];
        float va2 = g_aggv[n*192 + 128 + lane], vb2 = g_aggv[n*192 + 160 + lane];
        float at[4] = {attr[n*4+0], attr[n*4+1], attr[n*4+2], attr[n*4+3]};
        float os=0.f, ov0=0.f, ov1=0.f, ov2=0.f;
        for (int u = 0; u < 32; u++) {
            float su  = __shfl_sync(0xffffffffu, sa, u);
            float w0  = __shfl_sync(0xffffffffu, va0, u);
            float w1  = __shfl_sync(0xffffffffu, va1, u);
            float w2  = __shfl_sync(0xffffffffu, va2, u);
            int base = u*128 + lane;
#pragma unroll
            for (int a = 0; a < 4; a++) {
                float ca = at[a];
                int wi = base + a*32;
                os  += su*ca * s0[wi];
                float W = s1[wi];
                ov0 += w0*ca*W; ov1 += w1*ca*W; ov2 += w2*ca*W;
            }
        }
        for (int u = 0; u < 32; u++) {
            float su  = __shfl_sync(0xffffffffu, sb, u);
            float w0  = __shfl_sync(0xffffffffu, vb0, u);
            float w1  = __shfl_sync(0xffffffffu, vb1, u);
            float w2  = __shfl_sync(0xffffffffu, vb2, u);
            int base = (u+32)*128 + lane;
#pragma unroll
            for (int a = 0; a < 4; a++) {
                float ca = at[a];
                int wi = base + a*32;
                os  += su*ca * s0[wi];
                float W = s1[wi];
                ov0 += w0*ca*W; ov1 += w1*ca*W; ov2 += w2*ca*W;
            }
        }
        os *= NORM256; ov0 *= NORM256; ov1 *= NORM256; ov2 *= NORM256;
        float sn  = C_S * g_scs[n*32+lane] + C_X * os;
        float sig = 1.0f / (1.0f + __expf(-sn));
        g_s[n*32+lane] += sn * sig;
        float vn0 = C_S * g_scv[n*96+lane]      + C_X * ov0;
        float vn1 = C_S * g_scv[n*96+32+lane]   + C_X * ov1;
        float vn2 = C_S * g_scv[n*96+64+lane]   + C_X * ov2;
        g_v[n*96+lane]      += vn0 * sig;
        g_v[n*96+32+lane]   += vn1 * sig;
        g_v[n*96+64+lane]   += vn2 * sig;
    }
}

// ---------------- readout + pooling ----------------
__global__ void k_zero_out(float* out) { out[threadIdx.x] = 0.0f; }

__global__ void k_read(const float* __restrict__ attr, const int* __restrict__ batch,
                       const float* __restrict__ Wread, float* __restrict__ out,
                       int N, float poolscale) {
    __shared__ float shW[2048];
    __shared__ float pool[128];
    for (int i = threadIdx.x; i < 2048; i += blockDim.x) shW[i] = Wread[i];
    if (threadIdx.x < 128) pool[threadIdx.x] = 0.0f;
    __syncthreads();
    int lane = threadIdx.x & 31;
    int wid  = blockIdx.x * (blockDim.x >> 5) + (threadIdx.x >> 5);
    int wstr = gridDim.x * (blockDim.x >> 5);
    int w = lane & 15;
    for (int n = wid; n < N; n += wstr) {
        float sl = g_s[n*32 + lane];
        float at[4] = {attr[n*4+0], attr[n*4+1], attr[n*4+2], attr[n*4+3]};
        float acc = 0.f;
        for (int u = 0; u < 32; u++) {
            float su = __shfl_sync(0xffffffffu, sl, u);
            int base = u*64 + w;
#pragma unroll
            for (int a = 0; a < 4; a++) acc += su*at[a]*shW[base + a*16];
        }
        if (lane < 16) {
            int g = batch[n];
            atomicAdd(&pool[g*16 + w], acc * NORM128 * poolscale);
        }
    }
    __syncthreads();
    if (threadIdx.x < 128) atomicAdd(&out[threadIdx.x], pool[threadIdx.x]);
}

// ---------------- launcher ----------------
extern "C" void kernel_launch(void* const* d_in, const int* in_sizes, int n_in,
                              void* d_out, int out_size) {
    const float* x    = (const float*)d_in[0];
    const float* attr = (const float*)d_in[1];
    const float* evec = (const float*)d_in[2];
    const int*   batch= (const int*)  d_in[3];
    const int*   esrc = (const int*)  d_in[4];
    const int*   edst = (const int*)  d_in[5];
    const float* Wsc0 = (const float*)d_in[6];
    const float* Wsc1 = (const float*)d_in[7];
    const float* Wl10 = (const float*)d_in[8];
    const float* Wl11 = (const float*)d_in[9];
    const float* Wfc1 = (const float*)d_in[10];
    const float* Wfc2 = (const float*)d_in[11];
    const float* Wl20 = (const float*)d_in[12];
    const float* Wl21 = (const float*)d_in[13];
    const float* Wread= (const float*)d_in[14];
    int N = in_sizes[0] / 128;
    int E = in_sizes[4];

    cudaFuncSetAttribute(k_fusedA, cudaFuncAttributeMaxDynamicSharedMemorySize, 73728);
    cudaFuncSetAttribute(k_fusedB, cudaFuncAttributeMaxDynamicSharedMemorySize, 73728);
    cudaFuncSetAttribute(k_fctp1,  cudaFuncAttributeMaxDynamicSharedMemorySize, 65536);
    cudaFuncSetAttribute(k_fctp2,  cudaFuncAttributeMaxDynamicSharedMemorySize, 65536);

    // CSR build (by dst) + permuted precompute
    k_zero_deg<<<(N + 255) / 256, 256>>>(N);
    k_hist<<<(E + 255) / 256, 256>>>(edst, E);
    k_scan<<<1, SCAN_T>>>(N);
    k_fill<<<(E + 255) / 256, 256>>>(esrc, edst, E);
    k_pre_edges<<<(E + 255) / 256, 256>>>(evec, E);
    k_pre_nodes<<<(N*32 + 255) / 256, 256>>>(x, N);

    int nWG = (E + WG_TE - 1) / WG_TE;
    int nFC = 444;
    int nGB = (N + 1) / 2;

    // layer 0: wgemm0 || fctp1(0), then gather(0) || wgemm1
    k_fusedA<<<nWG + nFC, 256, 73728>>>(attr, Wsc0, Wsc1, Wl10, Wl11,
                                        Wfc1, Wfc2, N, E, nWG, nFC);
    k_fusedB<<<nWG + nGB, 256, 73728>>>(Wfc1 + 640, Wfc2 + 8192, N, E, nWG);
    k_fctp2<<<444, 256, 65536>>>(attr, Wl20, Wl21, N);

    // layer 1
    k_fctp1<<<444, 256, 65536>>>(attr, Wsc0 + 4096, Wsc1 + 4096,
                                 Wl10 + 4096, Wl11 + 4096, N);
    k_gather<<<nGB, 256>>>(N);
    k_fctp2<<<444, 256, 65536>>>(attr, Wl20 + 8192, Wl21 + 8192, N);

    k_zero_out<<<1, 128>>>((float*)d_out);
    float poolscale = 1.0f / sqrtf((float)N / 8.0f);
    k_read<<<592, 128>>>(attr, batch, Wread, (float*)d_out, N, poolscale);
}

// round 5
// speedup vs baseline: 1.1365x; 1.1365x over previous
#include <cuda_runtime.h>
#include <cuda_bf16.h>
#include <math.h>

#define MAXN 10000
#define MAXE 320000

// ---------------- scratch (device globals; no runtime alloc) ----------------
__device__ float g_s  [MAXN*32];
__device__ float g_v  [MAXN*96];    // (N,3,32)
__device__ float g_scs[MAXN*32];
__device__ float g_scv[MAXN*96];
__device__ float g_xs [MAXN*32];
__device__ float g_xv [MAXN*96];
__device__ float g_aggs[MAXN*64];
__device__ float g_aggv[MAXN*192];
// CSR (by dst) + permuted edge data
__device__ int   g_deg   [MAXN];
__device__ int   g_cursor[MAXN];
__device__ int   g_rowstart[MAXN+1];
__device__ int   g_slot  [MAXE];
__device__ int   g_srcP  [MAXE];
__device__ float g_embP  [MAXE*10];
__device__ float g_YP    [MAXE*3];
// per-edge radial weights, bf16
__device__ __nv_bfloat16 g_wb[MAXE*128];

// ---------------- constants ----------------
#define SQRT3F   1.7320508075688772f
#define ISQRT3F  0.5773502691896258f
#define INV_NB   0.17677669529663687f
#define NORM128  0.08838834764831845f
#define NORM256  0.0625f
#define INVS10   0.3162277660168379f
#define C_S      0.3826834323650898f
#define C_X      0.9238795325112867f
#define PI_F     3.14159265358979f
#define WG_TE    128

typedef unsigned long long ull;

// ---------------- packed f32x2 helpers ----------------
__device__ __forceinline__ ull pack2(float lo, float hi) {
    ull r;
    asm("mov.b64 %0, {%1, %2};" : "=l"(r) : "f"(lo), "f"(hi));
    return r;
}
__device__ __forceinline__ void ffma2(ull& acc, ull a, ull b) {
    asm("fma.rn.f32x2 %0, %1, %2, %0;" : "+l"(acc) : "l"(a), "l"(b));
}
__device__ __forceinline__ ull mul2r(ull a, ull b) {
    ull r;
    asm("mul.rn.f32x2 %0, %1, %2;" : "=l"(r) : "l"(a), "l"(b));
    return r;
}
__device__ __forceinline__ void mul2(ull& v, ull s) {
    asm("mul.rn.f32x2 %0, %0, %1;" : "+l"(v) : "l"(s));
}
__device__ __forceinline__ float2 unpack2(ull v) {
    float2 f;
    asm("mov.b64 {%0, %1}, %2;" : "=f"(f.x), "=f"(f.y) : "l"(v));
    return f;
}
__device__ __forceinline__ unsigned int bf16x2_of(float a, float b) {
    unsigned int r;
    asm("cvt.rn.bf16x2.f32 %0, %1, %2;" : "=r"(r) : "f"(b), "f"(a));
    return r;
}

// ---------------- CSR build ----------------
__global__ void k_zero_deg(int N) {
    int i = blockIdx.x * blockDim.x + threadIdx.x;
    if (i < N) g_deg[i] = 0;
}
__global__ void k_hist(const int* __restrict__ edst, int E) {
    int e = blockIdx.x * blockDim.x + threadIdx.x;
    if (e < E) atomicAdd(&g_deg[edst[e]], 1);
}
#define SCAN_T 1024
__global__ void k_scan(int N) {
    __shared__ int sums[SCAN_T];
    int t = threadIdx.x;
    int IT = (N + SCAN_T - 1) / SCAN_T;
    int lo = t * IT, hi = lo + IT; if (hi > N) hi = N; if (lo > N) lo = N;
    int s = 0;
    for (int i = lo; i < hi; i++) s += g_deg[i];
    sums[t] = s;
    __syncthreads();
    for (int off = 1; off < SCAN_T; off <<= 1) {
        int v = (t >= off) ? sums[t - off] : 0;
        __syncthreads();
        sums[t] += v;
        __syncthreads();
    }
    int run = (t == 0) ? 0 : sums[t - 1];
    for (int i = lo; i < hi; i++) {
        g_rowstart[i] = run;
        g_cursor[i]   = run;
        run += g_deg[i];
    }
    if (hi == N) g_rowstart[N] = run;
}
__global__ void k_fill(const int* __restrict__ esrc, const int* __restrict__ edst, int E) {
    int e = blockIdx.x * blockDim.x + threadIdx.x;
    if (e >= E) return;
    int pos = atomicAdd(&g_cursor[edst[e]], 1);
    g_slot[e] = pos;
    g_srcP[pos] = esrc[e];
}

// ---------------- precompute ----------------
__global__ void k_pre_edges(const float* __restrict__ evec, int E) {
    int e = blockIdx.x * blockDim.x + threadIdx.x;
    if (e >= E) return;
    int p = g_slot[e];
    float vx = evec[e*3+0], vy = evec[e*3+1], vz = evec[e*3+2];
    float len = sqrtf(vx*vx + vy*vy + vz*vz);
    float inv = 1.0f / (len + 1e-9f);
    g_YP[p*3+0] = SQRT3F * vx * inv;
    g_YP[p*3+1] = SQRT3F * vy * inv;
    g_YP[p*3+2] = SQRT3F * vz * inv;
    float u = 0.5f*len - 2.0f;
    float cut;
    if (u > 0.0f)       cut = 0.0f;
    else if (u < -1.0f) cut = 1.0f;
    else                cut = (1.0f - __cosf(PI_F * u)) * 0.5f;
#pragma unroll
    for (int b = 0; b < 10; b++) {
        float c = (4.0f/9.0f) * (float)b;
        float d = (len - c) * 2.5f;
        g_embP[p*10+b] = __expf(-d*d) * cut;
    }
}

__global__ void k_pre_nodes(const float* __restrict__ x, int N) {
    int i = blockIdx.x * blockDim.x + threadIdx.x;
    if (i >= N*32) return;
    int n = i >> 5, u = i & 31;
    g_s[i] = x[n*128 + u];
    g_v[n*96 +      u] = x[n*128 + 32 + u*3 + 0];
    g_v[n*96 + 32 + u] = x[n*128 + 32 + u*3 + 1];
    g_v[n*96 + 64 + u] = x[n*128 + 32 + u*3 + 2];
}

// ---------------- fctp #1: packed f32x2, interleaved weight pairs -----------
__global__ void __launch_bounds__(256)
k_fctp1(const float* __restrict__ attr,
        const float* __restrict__ W0, const float* __restrict__ W1,
        const float* __restrict__ L0, const float* __restrict__ L1, int N) {
    extern __shared__ float sm[];
    float2* sW02 = (float2*)sm;            // {W0[wi], L0[wi]}  4096 pairs
    float2* sW12 = (float2*)(sm + 8192);   // {W1[wi], L1[wi]}  4096 pairs
    for (int i = threadIdx.x; i < 4096; i += 256) {
        sW02[i] = make_float2(W0[i], L0[i]);
        sW12[i] = make_float2(W1[i], L1[i]);
    }
    __syncthreads();
    const ull* w02 = (const ull*)sW02;
    const ull* w12 = (const ull*)sW12;
    int lane = threadIdx.x & 31;
    int wid  = blockIdx.x * 8 + (threadIdx.x >> 5);
    int wstr = gridDim.x * 8;
    for (int n = wid; n < N; n += wstr) {
        float sl = g_s[n*32 + lane];
        float v0 = g_v[n*96 + lane];
        float v1 = g_v[n*96 + 32 + lane];
        float v2 = g_v[n*96 + 64 + lane];
        ull atp[4];
#pragma unroll
        for (int a = 0; a < 4; a++) { float av = attr[n*4+a]; atp[a] = pack2(av, av); }
        ull accS = 0ull, accV0 = 0ull, accV1 = 0ull, accV2 = 0ull;
        for (int u = 0; u < 32; u++) {
            float su  = __shfl_sync(0xffffffffu, sl, u);
            float vu0 = __shfl_sync(0xffffffffu, v0, u);
            float vu1 = __shfl_sync(0xffffffffu, v1, u);
            float vu2 = __shfl_sync(0xffffffffu, v2, u);
            ull sup = pack2(su, su);
            ull v0p = pack2(vu0, vu0);
            ull v1p = pack2(vu1, vu1);
            ull v2p = pack2(vu2, vu2);
            int base = u*128 + lane;
#pragma unroll
            for (int a = 0; a < 4; a++) {
                int wi = base + a*32;
                ull wa = w02[wi];
                ull wb = w12[wi];
                ffma2(accS,  mul2r(sup, atp[a]), wa);
                ffma2(accV0, mul2r(v0p, atp[a]), wb);
                ffma2(accV1, mul2r(v1p, atp[a]), wb);
                ffma2(accV2, mul2r(v2p, atp[a]), wb);
            }
        }
        float2 fS  = unpack2(accS);
        float2 fV0 = unpack2(accV0);
        float2 fV1 = unpack2(accV1);
        float2 fV2 = unpack2(accV2);
        g_scs[n*32+lane] = fS.x*NORM128;
        g_xs [n*32+lane] = fS.y*NORM128;
        g_scv[n*96+lane]      = fV0.x*NORM128;
        g_scv[n*96+32+lane]   = fV1.x*NORM128;
        g_scv[n*96+64+lane]   = fV2.x*NORM128;
        g_xv [n*96+lane]      = fV0.y*NORM128;
        g_xv [n*96+32+lane]   = fV1.y*NORM128;
        g_xv [n*96+64+lane]   = fV2.y*NORM128;
    }
}

// ---------------- w-GEMM: h = silu(emb@W1), w = h@W2/8 -> g_wb (bf16) -------
__global__ void __launch_bounds__(256)
k_wgemm(const float* __restrict__ Wfc1, const float* __restrict__ Wfc2, int E) {
    extern __shared__ float sm[];
    float* shW1  = sm;            // 640
    float* shW2  = sm + 640;      // 8192
    float* shEmb = sm + 8832;     // 1280
    float* shH   = sm + 10112;    // 8320 (stride 65)
    int tid = threadIdx.x;
    int eg0 = blockIdx.x * WG_TE;
    int nE = E - eg0; if (nE > WG_TE) nE = WG_TE;

    for (int i = tid; i < 640; i += 256) shW1[i] = Wfc1[i];
    for (int i = tid; i < 8192; i += 256) shW2[i] = Wfc2[i];
    for (int i = tid; i < WG_TE*10; i += 256) shEmb[i] = (i < nE*10) ? g_embP[eg0*10 + i] : 0.f;
    __syncthreads();

    for (int idx = tid; idx < WG_TE*64; idx += 256) {
        int e = idx >> 6, k = idx & 63;
        float acc = 0.f;
#pragma unroll
        for (int b = 0; b < 10; b++) acc += shEmb[e*10+b] * shW1[b*64+k];
        acc *= INVS10;
        shH[e*65 + k] = acc / (1.0f + __expf(-acc));
    }
    __syncthreads();

    int c0 = (tid & 15) * 8;
    int e0 = (tid >> 4) * 8;
    ull acc[8][4];
#pragma unroll
    for (int e = 0; e < 8; e++)
#pragma unroll
        for (int c = 0; c < 4; c++) acc[e][c] = 0ull;

#pragma unroll 4
    for (int k = 0; k < 64; k++) {
        const ull* Wrow = (const ull*)&shW2[k*128 + c0];
        ull w0 = Wrow[0], w1 = Wrow[1], w2 = Wrow[2], w3 = Wrow[3];
#pragma unroll
        for (int e = 0; e < 8; e++) {
            float hv = shH[(e0+e)*65 + k];
            ull hp = pack2(hv, hv);
            ffma2(acc[e][0], hp, w0);
            ffma2(acc[e][1], hp, w1);
            ffma2(acc[e][2], hp, w2);
            ffma2(acc[e][3], hp, w3);
        }
    }

    ull sc = pack2(0.125f, 0.125f);
#pragma unroll
    for (int e = 0; e < 8; e++) {
        int ge = eg0 + e0 + e;
        if (ge >= E) break;
        mul2(acc[e][0], sc); mul2(acc[e][1], sc);
        mul2(acc[e][2], sc); mul2(acc[e][3], sc);
        float2 f0 = unpack2(acc[e][0]);
        float2 f1 = unpack2(acc[e][1]);
        float2 f2 = unpack2(acc[e][2]);
        float2 f3 = unpack2(acc[e][3]);
        uint4 pk;
        pk.x = bf16x2_of(f0.x, f0.y);
        pk.y = bf16x2_of(f1.x, f1.y);
        pk.z = bf16x2_of(f2.x, f2.y);
        pk.w = bf16x2_of(f3.x, f3.y);
        *(uint4*)&g_wb[ge*128 + c0] = pk;
    }
}

// ---------------- gather: read bf16 w, gather features, accumulate ----------
__device__ void gather_node(int n, int sub) {
    int k = sub >> 5, u = sub & 31;
    int t0 = g_rowstart[n];
    int t1 = g_rowstart[n+1];
    float a0 = 0.f, a1 = 0.f, a2 = 0.f;

    if (k == 0) {
        int e = t0;
        for (; e + 4 <= t1; e += 4) {
            int s0 = g_srcP[e], s1 = g_srcP[e+1], s2 = g_srcP[e+2], s3 = g_srcP[e+3];
            float w0 = __bfloat162float(g_wb[(e+0)*128 + sub]);
            float w1 = __bfloat162float(g_wb[(e+1)*128 + sub]);
            float w2 = __bfloat162float(g_wb[(e+2)*128 + sub]);
            float w3 = __bfloat162float(g_wb[(e+3)*128 + sub]);
            a0 += w0 * g_xs[s0*32 + u];
            a1 += w1 * g_xs[s1*32 + u];
            a0 += w2 * g_xs[s2*32 + u];
            a1 += w3 * g_xs[s3*32 + u];
        }
        for (; e < t1; e++)
            a0 += __bfloat162float(g_wb[e*128 + sub]) * g_xs[g_srcP[e]*32 + u];
        g_aggs[n*64 + u] = (a0 + a1) * INV_NB;
    } else if (k == 1) {
        int e = t0;
        for (; e + 2 <= t1; e += 2) {
            int s0 = g_srcP[e], s1 = g_srcP[e+1];
            float w0 = __bfloat162float(g_wb[(e+0)*128 + sub]);
            float w1 = __bfloat162float(g_wb[(e+1)*128 + sub]);
            float d0 = g_YP[e*3+0]*g_xv[s0*96+u] + g_YP[e*3+1]*g_xv[s0*96+32+u]
                     + g_YP[e*3+2]*g_xv[s0*96+64+u];
            float d1 = g_YP[e*3+3]*g_xv[s1*96+u] + g_YP[e*3+4]*g_xv[s1*96+32+u]
                     + g_YP[e*3+5]*g_xv[s1*96+64+u];
            a0 += w0 * d0;
            a1 += w1 * d1;
        }
        for (; e < t1; e++) {
            int s0 = g_srcP[e];
            float w = __bfloat162float(g_wb[e*128 + sub]);
            a0 += w * (g_YP[e*3+0]*g_xv[s0*96+u] + g_YP[e*3+1]*g_xv[s0*96+32+u]
                     + g_YP[e*3+2]*g_xv[s0*96+64+u]);
        }
        g_aggs[n*64 + 32 + u] = (a0 + a1) * ISQRT3F * INV_NB;
    } else if (k == 2) {
        for (int e = t0; e < t1; e++) {
            float m = __bfloat162float(g_wb[e*128 + sub]) * g_xs[g_srcP[e]*32 + u];
            a0 += m * g_YP[e*3+0];
            a1 += m * g_YP[e*3+1];
            a2 += m * g_YP[e*3+2];
        }
        g_aggv[n*192 +       u] = a0 * INV_NB;
        g_aggv[n*192 +  64 + u] = a1 * INV_NB;
        g_aggv[n*192 + 128 + u] = a2 * INV_NB;
    } else {
        for (int e = t0; e < t1; e++) {
            float w = __bfloat162float(g_wb[e*128 + sub]);
            int src = g_srcP[e];
            a0 += w * g_xv[src*96 + u];
            a1 += w * g_xv[src*96 + 32 + u];
            a2 += w * g_xv[src*96 + 64 + u];
        }
        g_aggv[n*192 +  32 + u] = a0 * INV_NB;
        g_aggv[n*192 +  96 + u] = a1 * INV_NB;
        g_aggv[n*192 + 160 + u] = a2 * INV_NB;
    }
}

__global__ void __launch_bounds__(256)
k_gather(int N) {
    int n = blockIdx.x*2 + (threadIdx.x >> 7);
    if (n < N) gather_node(n, threadIdx.x & 127);
}

// ---------------- fctp #2: packed f32x2 + gated state update ----------------
__global__ void __launch_bounds__(256)
k_fctp2(const float* __restrict__ attr,
        const float* __restrict__ W20, const float* __restrict__ W21, int N) {
    extern __shared__ float sm[];
    float2* sWp = (float2*)sm;   // {W20[wi], W21[wi]}  8192 pairs = 64 KB
    for (int i = threadIdx.x; i < 8192; i += 256)
        sWp[i] = make_float2(W20[i], W21[i]);
    __syncthreads();
    const ull* wPair = (const ull*)sWp;
    int lane = threadIdx.x & 31;
    int wid  = blockIdx.x * 8 + (threadIdx.x >> 5);
    int wstr = gridDim.x * 8;
    for (int n = wid; n < N; n += wstr) {
        float sa  = g_aggs[n*64 + lane],        sb  = g_aggs[n*64 + 32 + lane];
        float va0 = g_aggv[n*192 + lane],       vb0 = g_aggv[n*192 + 32 + lane];
        float va1 = g_aggv[n*192 + 64 + lane],  vb1 = g_aggv[n*192 + 96 + lane];
        float va2 = g_aggv[n*192 + 128 + lane], vb2 = g_aggv[n*192 + 160 + lane];
        ull atp[4];
#pragma unroll
        for (int a = 0; a < 4; a++) { float av = attr[n*4+a]; atp[a] = pack2(av, av); }
        ull accA = 0ull;   // {os, ov2}
        ull accB = 0ull;   // {ov0, ov1}
#pragma unroll 1
        for (int half = 0; half < 2; half++) {
            float ss  = half ? sb  : sa;
            float vv0 = half ? vb0 : va0;
            float vv1 = half ? vb1 : va1;
            float vv2 = half ? vb2 : va2;
            int uoff = half ? 32 : 0;
            for (int u = 0; u < 32; u++) {
                float su = __shfl_sync(0xffffffffu, ss,  u);
                float w0 = __shfl_sync(0xffffffffu, vv0, u);
                float w1 = __shfl_sync(0xffffffffu, vv1, u);
                float w2 = __shfl_sync(0xffffffffu, vv2, u);
                ull pA = pack2(su, w2);
                ull pB = pack2(w0, w1);
                int base = (u + uoff)*128 + lane;
#pragma unroll
                for (int a = 0; a < 4; a++) {
                    int wi = base + a*32;
                    ull wp = wPair[wi];
                    float2 wf = unpack2(wp);
                    ull wdup = pack2(wf.y, wf.y);
                    ffma2(accA, mul2r(pA, atp[a]), wp);
                    ffma2(accB, mul2r(pB, atp[a]), wdup);
                }
            }
        }
        float2 fA = unpack2(accA);   // {os, ov2}
        float2 fB = unpack2(accB);   // {ov0, ov1}
        float os  = fA.x*NORM256, ov2 = fA.y*NORM256;
        float ov0 = fB.x*NORM256, ov1 = fB.y*NORM256;
        float sn  = C_S * g_scs[n*32+lane] + C_X * os;
        float sig = 1.0f / (1.0f + __expf(-sn));
        g_s[n*32+lane] += sn * sig;
        float vn0 = C_S * g_scv[n*96+lane]      + C_X * ov0;
        float vn1 = C_S * g_scv[n*96+32+lane]   + C_X * ov1;
        float vn2 = C_S * g_scv[n*96+64+lane]   + C_X * ov2;
        g_v[n*96+lane]      += vn0 * sig;
        g_v[n*96+32+lane]   += vn1 * sig;
        g_v[n*96+64+lane]   += vn2 * sig;
    }
}

// ---------------- readout + pooling ----------------
__global__ void k_zero_out(float* out) { out[threadIdx.x] = 0.0f; }

__global__ void k_read(const float* __restrict__ attr, const int* __restrict__ batch,
                       const float* __restrict__ Wread, float* __restrict__ out,
                       int N, float poolscale) {
    __shared__ float shW[2048];
    __shared__ float pool[128];
    for (int i = threadIdx.x; i < 2048; i += blockDim.x) shW[i] = Wread[i];
    if (threadIdx.x < 128) pool[threadIdx.x] = 0.0f;
    __syncthreads();
    int lane = threadIdx.x & 31;
    int wid  = blockIdx.x * (blockDim.x >> 5) + (threadIdx.x >> 5);
    int wstr = gridDim.x * (blockDim.x >> 5);
    int w = lane & 15;
    for (int n = wid; n < N; n += wstr) {
        float sl = g_s[n*32 + lane];
        float at[4] = {attr[n*4+0], attr[n*4+1], attr[n*4+2], attr[n*4+3]};
        float acc = 0.f;
        for (int u = 0; u < 32; u++) {
            float su = __shfl_sync(0xffffffffu, sl, u);
            int base = u*64 + w;
#pragma unroll
            for (int a = 0; a < 4; a++) acc += su*at[a]*shW[base + a*16];
        }
        if (lane < 16) {
            int g = batch[n];
            atomicAdd(&pool[g*16 + w], acc * NORM128 * poolscale);
        }
    }
    __syncthreads();
    if (threadIdx.x < 128) atomicAdd(&out[threadIdx.x], pool[threadIdx.x]);
}

// ---------------- launcher ----------------
extern "C" void kernel_launch(void* const* d_in, const int* in_sizes, int n_in,
                              void* d_out, int out_size) {
    const float* x    = (const float*)d_in[0];
    const float* attr = (const float*)d_in[1];
    const float* evec = (const float*)d_in[2];
    const int*   batch= (const int*)  d_in[3];
    const int*   esrc = (const int*)  d_in[4];
    const int*   edst = (const int*)  d_in[5];
    const float* Wsc0 = (const float*)d_in[6];
    const float* Wsc1 = (const float*)d_in[7];
    const float* Wl10 = (const float*)d_in[8];
    const float* Wl11 = (const float*)d_in[9];
    const float* Wfc1 = (const float*)d_in[10];
    const float* Wfc2 = (const float*)d_in[11];
    const float* Wl20 = (const float*)d_in[12];
    const float* Wl21 = (const float*)d_in[13];
    const float* Wread= (const float*)d_in[14];
    int N = in_sizes[0] / 128;
    int E = in_sizes[4];

    cudaFuncSetAttribute(k_fctp1, cudaFuncAttributeMaxDynamicSharedMemorySize, 65536);
    cudaFuncSetAttribute(k_fctp2, cudaFuncAttributeMaxDynamicSharedMemorySize, 65536);
    cudaFuncSetAttribute(k_wgemm, cudaFuncAttributeMaxDynamicSharedMemorySize, 73728);

    // CSR build (by dst) + permuted precompute
    k_zero_deg<<<(N + 255) / 256, 256>>>(N);
    k_hist<<<(E + 255) / 256, 256>>>(edst, E);
    k_scan<<<1, SCAN_T>>>(N);
    k_fill<<<(E + 255) / 256, 256>>>(esrc, edst, E);
    k_pre_edges<<<(E + 255) / 256, 256>>>(evec, E);
    k_pre_nodes<<<(N*32 + 255) / 256, 256>>>(x, N);

    int nWG = (E + WG_TE - 1) / WG_TE;
    int nGB = (N + 1) / 2;

    for (int l = 0; l < 2; l++) {
        k_fctp1<<<444, 256, 65536>>>(attr, Wsc0 + l*4096, Wsc1 + l*4096,
                                     Wl10 + l*4096, Wl11 + l*4096, N);
        k_wgemm<<<nWG, 256, 73728>>>(Wfc1 + l*640, Wfc2 + l*8192, E);
        k_gather<<<nGB, 256>>>(N);
        k_fctp2<<<444, 256, 65536>>>(attr, Wl20 + l*8192, Wl21 + l*8192, N);
    }

    k_zero_out<<<1, 128>>>((float*)d_out);
    float poolscale = 1.0f / sqrtf((float)N / 8.0f);
    k_read<<<592, 128>>>(attr, batch, Wread, (float*)d_out, N, poolscale);
}

// round 6
// speedup vs baseline: 1.1955x; 1.0519x over previous
#include <cuda_runtime.h>
#include <cuda_bf16.h>
#include <math.h>

#define MAXN 10000
#define MAXE 320000

// ---------------- scratch (device globals; no runtime alloc) ----------------
__device__ float g_s  [MAXN*32];
__device__ float g_v  [MAXN*96];    // (N,3,32)
__device__ float g_scs[MAXN*32];
__device__ float g_scv[MAXN*96];
__device__ float g_xs [MAXN*32];
__device__ float g_xv [MAXN*96];
__device__ float g_aggs[MAXN*64];
__device__ float g_aggv[MAXN*192];
// CSR (by dst) + permuted edge data
__device__ int   g_deg   [MAXN];
__device__ int   g_cursor[MAXN];
__device__ int   g_rowstart[MAXN+1];
__device__ int   g_slot  [MAXE];
__device__ int   g_srcP  [MAXE];
__device__ float g_embP  [MAXE*10];
__device__ float g_YP    [MAXE*3];
// per-edge radial weights, bf16, double-buffered per layer
__device__ __nv_bfloat16 g_wb0[MAXE*128];
__device__ __nv_bfloat16 g_wb1[MAXE*128];

// ---------------- constants ----------------
#define SQRT3F   1.7320508075688772f
#define ISQRT3F  0.5773502691896258f
#define INV_NB   0.17677669529663687f
#define NORM128  0.08838834764831845f
#define NORM256  0.0625f
#define INVS10   0.3162277660168379f
#define C_S      0.3826834323650898f
#define C_X      0.9238795325112867f
#define PI_F     3.14159265358979f
#define WG_TE    128
#define FUSED_SMEM 73728

typedef unsigned long long ull;

// ---------------- packed f32x2 helpers ----------------
__device__ __forceinline__ ull pack2(float lo, float hi) {
    ull r;
    asm("mov.b64 %0, {%1, %2};" : "=l"(r) : "f"(lo), "f"(hi));
    return r;
}
__device__ __forceinline__ void ffma2(ull& acc, ull a, ull b) {
    asm("fma.rn.f32x2 %0, %1, %2, %0;" : "+l"(acc) : "l"(a), "l"(b));
}
__device__ __forceinline__ ull mul2r(ull a, ull b) {
    ull r;
    asm("mul.rn.f32x2 %0, %1, %2;" : "=l"(r) : "l"(a), "l"(b));
    return r;
}
__device__ __forceinline__ void mul2(ull& v, ull s) {
    asm("mul.rn.f32x2 %0, %0, %1;" : "+l"(v) : "l"(s));
}
__device__ __forceinline__ float2 unpack2(ull v) {
    float2 f;
    asm("mov.b64 {%0, %1}, %2;" : "=f"(f.x), "=f"(f.y) : "l"(v));
    return f;
}
__device__ __forceinline__ unsigned int bf16x2_of(float a, float b) {
    unsigned int r;
    asm("cvt.rn.bf16x2.f32 %0, %1, %2;" : "=r"(r) : "f"(b), "f"(a));
    return r;
}

// ---------------- CSR build ----------------
__global__ void k_zero_deg(int N) {
    int i = blockIdx.x * blockDim.x + threadIdx.x;
    if (i < N) g_deg[i] = 0;
}
__global__ void k_hist(const int* __restrict__ edst, int E) {
    int e = blockIdx.x * blockDim.x + threadIdx.x;
    if (e < E) atomicAdd(&g_deg[edst[e]], 1);
}
#define SCAN_T 1024
__global__ void k_scan(int N) {
    __shared__ int sums[SCAN_T];
    int t = threadIdx.x;
    int IT = (N + SCAN_T - 1) / SCAN_T;
    int lo = t * IT, hi = lo + IT; if (hi > N) hi = N; if (lo > N) lo = N;
    int s = 0;
    for (int i = lo; i < hi; i++) s += g_deg[i];
    sums[t] = s;
    __syncthreads();
    for (int off = 1; off < SCAN_T; off <<= 1) {
        int v = (t >= off) ? sums[t - off] : 0;
        __syncthreads();
        sums[t] += v;
        __syncthreads();
    }
    int run = (t == 0) ? 0 : sums[t - 1];
    for (int i = lo; i < hi; i++) {
        g_rowstart[i] = run;
        g_cursor[i]   = run;
        run += g_deg[i];
    }
    if (hi == N) g_rowstart[N] = run;
}
__global__ void k_fill(const int* __restrict__ esrc, const int* __restrict__ edst, int E) {
    int e = blockIdx.x * blockDim.x + threadIdx.x;
    if (e >= E) return;
    int pos = atomicAdd(&g_cursor[edst[e]], 1);
    g_slot[e] = pos;
    g_srcP[pos] = esrc[e];
}

// ---------------- precompute ----------------
__global__ void k_pre_edges(const float* __restrict__ evec, int E) {
    int e = blockIdx.x * blockDim.x + threadIdx.x;
    if (e >= E) return;
    int p = g_slot[e];
    float vx = evec[e*3+0], vy = evec[e*3+1], vz = evec[e*3+2];
    float len = sqrtf(vx*vx + vy*vy + vz*vz);
    float inv = 1.0f / (len + 1e-9f);
    g_YP[p*3+0] = SQRT3F * vx * inv;
    g_YP[p*3+1] = SQRT3F * vy * inv;
    g_YP[p*3+2] = SQRT3F * vz * inv;
    float u = 0.5f*len - 2.0f;
    float cut;
    if (u > 0.0f)       cut = 0.0f;
    else if (u < -1.0f) cut = 1.0f;
    else                cut = (1.0f - __cosf(PI_F * u)) * 0.5f;
#pragma unroll
    for (int b = 0; b < 10; b++) {
        float c = (4.0f/9.0f) * (float)b;
        float d = (len - c) * 2.5f;
        g_embP[p*10+b] = __expf(-d*d) * cut;
    }
}

__global__ void k_pre_nodes(const float* __restrict__ x, int N) {
    int i = blockIdx.x * blockDim.x + threadIdx.x;
    if (i >= N*32) return;
    int n = i >> 5, u = i & 31;
    g_s[i] = x[n*128 + u];
    g_v[n*96 +      u] = x[n*128 + 32 + u*3 + 0];
    g_v[n*96 + 32 + u] = x[n*128 + 32 + u*3 + 1];
    g_v[n*96 + 64 + u] = x[n*128 + 32 + u*3 + 2];
}

// ================= device bodies ======================

// --- fctp1: packed f32x2, interleaved weight pairs (16 KB smem used) ---
__device__ void fctp1_dev(float* sm, const float* __restrict__ attr,
                          const float* __restrict__ W0, const float* __restrict__ W1,
                          const float* __restrict__ L0, const float* __restrict__ L1,
                          int N, int relBid, int nBlocks) {
    float2* sW02 = (float2*)sm;            // {W0, L0} pairs
    float2* sW12 = (float2*)(sm + 8192);   // {W1, L1} pairs
    for (int i = threadIdx.x; i < 4096; i += 256) {
        sW02[i] = make_float2(W0[i], L0[i]);
        sW12[i] = make_float2(W1[i], L1[i]);
    }
    __syncthreads();
    const ull* w02 = (const ull*)sW02;
    const ull* w12 = (const ull*)sW12;
    int lane = threadIdx.x & 31;
    int wid  = relBid * 8 + (threadIdx.x >> 5);
    int wstr = nBlocks * 8;
    for (int n = wid; n < N; n += wstr) {
        float sl = g_s[n*32 + lane];
        float v0 = g_v[n*96 + lane];
        float v1 = g_v[n*96 + 32 + lane];
        float v2 = g_v[n*96 + 64 + lane];
        ull atp[4];
#pragma unroll
        for (int a = 0; a < 4; a++) { float av = attr[n*4+a]; atp[a] = pack2(av, av); }
        ull accS = 0ull, accV0 = 0ull, accV1 = 0ull, accV2 = 0ull;
        for (int u = 0; u < 32; u++) {
            float su  = __shfl_sync(0xffffffffu, sl, u);
            float vu0 = __shfl_sync(0xffffffffu, v0, u);
            float vu1 = __shfl_sync(0xffffffffu, v1, u);
            float vu2 = __shfl_sync(0xffffffffu, v2, u);
            ull sup = pack2(su, su);
            ull v0p = pack2(vu0, vu0);
            ull v1p = pack2(vu1, vu1);
            ull v2p = pack2(vu2, vu2);
            int base = u*128 + lane;
#pragma unroll
            for (int a = 0; a < 4; a++) {
                int wi = base + a*32;
                ull wa = w02[wi];
                ull wb = w12[wi];
                ffma2(accS,  mul2r(sup, atp[a]), wa);
                ffma2(accV0, mul2r(v0p, atp[a]), wb);
                ffma2(accV1, mul2r(v1p, atp[a]), wb);
                ffma2(accV2, mul2r(v2p, atp[a]), wb);
            }
        }
        float2 fS  = unpack2(accS);
        float2 fV0 = unpack2(accV0);
        float2 fV1 = unpack2(accV1);
        float2 fV2 = unpack2(accV2);
        g_scs[n*32+lane] = fS.x*NORM128;
        g_xs [n*32+lane] = fS.y*NORM128;
        g_scv[n*96+lane]      = fV0.x*NORM128;
        g_scv[n*96+32+lane]   = fV1.x*NORM128;
        g_scv[n*96+64+lane]   = fV2.x*NORM128;
        g_xv [n*96+lane]      = fV0.y*NORM128;
        g_xv [n*96+32+lane]   = fV1.y*NORM128;
        g_xv [n*96+64+lane]   = fV2.y*NORM128;
    }
}

// --- wgemm: h = silu(emb@W1), w = h@W2/8 -> bf16 out (72 KB smem used) ---
__device__ void wgemm_dev(float* sm, const float* __restrict__ Wfc1,
                          const float* __restrict__ Wfc2,
                          __nv_bfloat16* __restrict__ wout, int E, int bid) {
    float* shW1  = sm;            // 640
    float* shW2  = sm + 640;      // 8192
    float* shEmb = sm + 8832;     // 1280
    float* shH   = sm + 10112;    // 8320 (stride 65)
    int tid = threadIdx.x;
    int eg0 = bid * WG_TE;
    int nE = E - eg0; if (nE > WG_TE) nE = WG_TE;

    for (int i = tid; i < 640; i += 256) shW1[i] = Wfc1[i];
    for (int i = tid; i < 8192; i += 256) shW2[i] = Wfc2[i];
    for (int i = tid; i < WG_TE*10; i += 256) shEmb[i] = (i < nE*10) ? g_embP[eg0*10 + i] : 0.f;
    __syncthreads();

    for (int idx = tid; idx < WG_TE*64; idx += 256) {
        int e = idx >> 6, k = idx & 63;
        float acc = 0.f;
#pragma unroll
        for (int b = 0; b < 10; b++) acc += shEmb[e*10+b] * shW1[b*64+k];
        acc *= INVS10;
        shH[e*65 + k] = acc / (1.0f + __expf(-acc));
    }
    __syncthreads();

    int c0 = (tid & 15) * 8;
    int e0 = (tid >> 4) * 8;
    ull acc[8][4];
#pragma unroll
    for (int e = 0; e < 8; e++)
#pragma unroll
        for (int c = 0; c < 4; c++) acc[e][c] = 0ull;

#pragma unroll 4
    for (int k = 0; k < 64; k++) {
        const ull* Wrow = (const ull*)&shW2[k*128 + c0];
        ull w0 = Wrow[0], w1 = Wrow[1], w2 = Wrow[2], w3 = Wrow[3];
#pragma unroll
        for (int e = 0; e < 8; e++) {
            float hv = shH[(e0+e)*65 + k];
            ull hp = pack2(hv, hv);
            ffma2(acc[e][0], hp, w0);
            ffma2(acc[e][1], hp, w1);
            ffma2(acc[e][2], hp, w2);
            ffma2(acc[e][3], hp, w3);
        }
    }

    ull sc = pack2(0.125f, 0.125f);
#pragma unroll
    for (int e = 0; e < 8; e++) {
        int ge = eg0 + e0 + e;
        if (ge >= E) break;
        mul2(acc[e][0], sc); mul2(acc[e][1], sc);
        mul2(acc[e][2], sc); mul2(acc[e][3], sc);
        float2 f0 = unpack2(acc[e][0]);
        float2 f1 = unpack2(acc[e][1]);
        float2 f2 = unpack2(acc[e][2]);
        float2 f3 = unpack2(acc[e][3]);
        uint4 pk;
        pk.x = bf16x2_of(f0.x, f0.y);
        pk.y = bf16x2_of(f1.x, f1.y);
        pk.z = bf16x2_of(f2.x, f2.y);
        pk.w = bf16x2_of(f3.x, f3.y);
        *(uint4*)&wout[ge*128 + c0] = pk;
    }
}

// --- fctp2: packed f32x2 + gated state update (64 KB smem used) ---
__device__ void fctp2_dev(float* sm, const float* __restrict__ attr,
                          const float* __restrict__ W20, const float* __restrict__ W21,
                          int N, int relBid, int nBlocks) {
    float2* sWp = (float2*)sm;   // {W20, W21} pairs, 8192
    for (int i = threadIdx.x; i < 8192; i += 256)
        sWp[i] = make_float2(W20[i], W21[i]);
    __syncthreads();
    const ull* wPair = (const ull*)sWp;
    int lane = threadIdx.x & 31;
    int wid  = relBid * 8 + (threadIdx.x >> 5);
    int wstr = nBlocks * 8;
    for (int n = wid; n < N; n += wstr) {
        float sa  = g_aggs[n*64 + lane],        sb  = g_aggs[n*64 + 32 + lane];
        float va0 = g_aggv[n*192 + lane],       vb0 = g_aggv[n*192 + 32 + lane];
        float va1 = g_aggv[n*192 + 64 + lane],  vb1 = g_aggv[n*192 + 96 + lane];
        float va2 = g_aggv[n*192 + 128 + lane], vb2 = g_aggv[n*192 + 160 + lane];
        ull atp[4];
#pragma unroll
        for (int a = 0; a < 4; a++) { float av = attr[n*4+a]; atp[a] = pack2(av, av); }
        ull accA = 0ull;   // {os, ov2}
        ull accB = 0ull;   // {ov0, ov1}
#pragma unroll 1
        for (int half = 0; half < 2; half++) {
            float ss  = half ? sb  : sa;
            float vv0 = half ? vb0 : va0;
            float vv1 = half ? vb1 : va1;
            float vv2 = half ? vb2 : va2;
            int uoff = half ? 32 : 0;
            for (int u = 0; u < 32; u++) {
                float su = __shfl_sync(0xffffffffu, ss,  u);
                float w0 = __shfl_sync(0xffffffffu, vv0, u);
                float w1 = __shfl_sync(0xffffffffu, vv1, u);
                float w2 = __shfl_sync(0xffffffffu, vv2, u);
                ull pA = pack2(su, w2);
                ull pB = pack2(w0, w1);
                int base = (u + uoff)*128 + lane;
#pragma unroll
                for (int a = 0; a < 4; a++) {
                    int wi = base + a*32;
                    ull wp = wPair[wi];
                    float2 wf = unpack2(wp);
                    ull wdup = pack2(wf.y, wf.y);
                    ffma2(accA, mul2r(pA, atp[a]), wp);
                    ffma2(accB, mul2r(pB, atp[a]), wdup);
                }
            }
        }
        float2 fA = unpack2(accA);
        float2 fB = unpack2(accB);
        float os  = fA.x*NORM256, ov2 = fA.y*NORM256;
        float ov0 = fB.x*NORM256, ov1 = fB.y*NORM256;
        float sn  = C_S * g_scs[n*32+lane] + C_X * os;
        float sig = 1.0f / (1.0f + __expf(-sn));
        g_s[n*32+lane] += sn * sig;
        float vn0 = C_S * g_scv[n*96+lane]      + C_X * ov0;
        float vn1 = C_S * g_scv[n*96+32+lane]   + C_X * ov1;
        float vn2 = C_S * g_scv[n*96+64+lane]   + C_X * ov2;
        g_v[n*96+lane]      += vn0 * sig;
        g_v[n*96+32+lane]   += vn1 * sig;
        g_v[n*96+64+lane]   += vn2 * sig;
    }
}

// --- gather body (no smem; needs full occupancy) ---
__device__ void gather_node(const __nv_bfloat16* __restrict__ win, int n, int sub) {
    int k = sub >> 5, u = sub & 31;
    int t0 = g_rowstart[n];
    int t1 = g_rowstart[n+1];
    float a0 = 0.f, a1 = 0.f, a2 = 0.f;

    if (k == 0) {
        int e = t0;
        for (; e + 4 <= t1; e += 4) {
            int s0 = g_srcP[e], s1 = g_srcP[e+1], s2 = g_srcP[e+2], s3 = g_srcP[e+3];
            float w0 = __bfloat162float(win[(e+0)*128 + sub]);
            float w1 = __bfloat162float(win[(e+1)*128 + sub]);
            float w2 = __bfloat162float(win[(e+2)*128 + sub]);
            float w3 = __bfloat162float(win[(e+3)*128 + sub]);
            a0 += w0 * g_xs[s0*32 + u];
            a1 += w1 * g_xs[s1*32 + u];
            a0 += w2 * g_xs[s2*32 + u];
            a1 += w3 * g_xs[s3*32 + u];
        }
        for (; e < t1; e++)
            a0 += __bfloat162float(win[e*128 + sub]) * g_xs[g_srcP[e]*32 + u];
        g_aggs[n*64 + u] = (a0 + a1) * INV_NB;
    } else if (k == 1) {
        int e = t0;
        for (; e + 2 <= t1; e += 2) {
            int s0 = g_srcP[e], s1 = g_srcP[e+1];
            float w0 = __bfloat162float(win[(e+0)*128 + sub]);
            float w1 = __bfloat162float(win[(e+1)*128 + sub]);
            float d0 = g_YP[e*3+0]*g_xv[s0*96+u] + g_YP[e*3+1]*g_xv[s0*96+32+u]
                     + g_YP[e*3+2]*g_xv[s0*96+64+u];
            float d1 = g_YP[e*3+3]*g_xv[s1*96+u] + g_YP[e*3+4]*g_xv[s1*96+32+u]
                     + g_YP[e*3+5]*g_xv[s1*96+64+u];
            a0 += w0 * d0;
            a1 += w1 * d1;
        }
        for (; e < t1; e++) {
            int s0 = g_srcP[e];
            float w = __bfloat162float(win[e*128 + sub]);
            a0 += w * (g_YP[e*3+0]*g_xv[s0*96+u] + g_YP[e*3+1]*g_xv[s0*96+32+u]
                     + g_YP[e*3+2]*g_xv[s0*96+64+u]);
        }
        g_aggs[n*64 + 32 + u] = (a0 + a1) * ISQRT3F * INV_NB;
    } else if (k == 2) {
        for (int e = t0; e < t1; e++) {
            float m = __bfloat162float(win[e*128 + sub]) * g_xs[g_srcP[e]*32 + u];
            a0 += m * g_YP[e*3+0];
            a1 += m * g_YP[e*3+1];
            a2 += m * g_YP[e*3+2];
        }
        g_aggv[n*192 +       u] = a0 * INV_NB;
        g_aggv[n*192 +  64 + u] = a1 * INV_NB;
        g_aggv[n*192 + 128 + u] = a2 * INV_NB;
    } else {
        for (int e = t0; e < t1; e++) {
            float w = __bfloat162float(win[e*128 + sub]);
            int src = g_srcP[e];
            a0 += w * g_xv[src*96 + u];
            a1 += w * g_xv[src*96 + 32 + u];
            a2 += w * g_xv[src*96 + 64 + u];
        }
        g_aggv[n*192 +  32 + u] = a0 * INV_NB;
        g_aggv[n*192 +  96 + u] = a1 * INV_NB;
        g_aggv[n*192 + 160 + u] = a2 * INV_NB;
    }
}

// ================= launches ======================

// A: wgemm(L0)->wb0 || fctp1(L0)
__global__ void __launch_bounds__(256)
k_fusedA(const float* __restrict__ attr,
         const float* __restrict__ W0, const float* __restrict__ W1,
         const float* __restrict__ L0, const float* __restrict__ L1,
         const float* __restrict__ Wfc1, const float* __restrict__ Wfc2,
         int N, int E, int nWG, int nFC) {
    extern __shared__ float sm[];
    if ((int)blockIdx.x < nWG) wgemm_dev(sm, Wfc1, Wfc2, g_wb0, E, blockIdx.x);
    else fctp1_dev(sm, attr, W0, W1, L0, L1, N, blockIdx.x - nWG, nFC);
}

// C: wgemm(L1)->wb1 || fctp2(L0)
__global__ void __launch_bounds__(256)
k_fusedC(const float* __restrict__ attr,
         const float* __restrict__ W20, const float* __restrict__ W21,
         const float* __restrict__ Wfc1, const float* __restrict__ Wfc2,
         int N, int E, int nWG, int nFC) {
    extern __shared__ float sm[];
    if ((int)blockIdx.x < nWG) wgemm_dev(sm, Wfc1, Wfc2, g_wb1, E, blockIdx.x);
    else fctp2_dev(sm, attr, W20, W21, N, blockIdx.x - nWG, nFC);
}

__global__ void __launch_bounds__(256)
k_gather0(int N) {
    int n = blockIdx.x*2 + (threadIdx.x >> 7);
    if (n < N) gather_node(g_wb0, n, threadIdx.x & 127);
}
__global__ void __launch_bounds__(256)
k_gather1(int N) {
    int n = blockIdx.x*2 + (threadIdx.x >> 7);
    if (n < N) gather_node(g_wb1, n, threadIdx.x & 127);
}

__global__ void __launch_bounds__(256)
k_fctp1(const float* __restrict__ attr,
        const float* __restrict__ W0, const float* __restrict__ W1,
        const float* __restrict__ L0, const float* __restrict__ L1, int N) {
    extern __shared__ float sm[];
    fctp1_dev(sm, attr, W0, W1, L0, L1, N, blockIdx.x, gridDim.x);
}

__global__ void __launch_bounds__(256)
k_fctp2(const float* __restrict__ attr,
        const float* __restrict__ W20, const float* __restrict__ W21, int N) {
    extern __shared__ float sm[];
    fctp2_dev(sm, attr, W20, W21, N, blockIdx.x, gridDim.x);
}

// ---------------- readout + pooling ----------------
__global__ void k_zero_out(float* out) { out[threadIdx.x] = 0.0f; }

__global__ void k_read(const float* __restrict__ attr, const int* __restrict__ batch,
                       const float* __restrict__ Wread, float* __restrict__ out,
                       int N, float poolscale) {
    __shared__ float shW[2048];
    __shared__ float pool[128];
    for (int i = threadIdx.x; i < 2048; i += blockDim.x) shW[i] = Wread[i];
    if (threadIdx.x < 128) pool[threadIdx.x] = 0.0f;
    __syncthreads();
    int lane = threadIdx.x & 31;
    int wid  = blockIdx.x * (blockDim.x >> 5) + (threadIdx.x >> 5);
    int wstr = gridDim.x * (blockDim.x >> 5);
    int w = lane & 15;
    for (int n = wid; n < N; n += wstr) {
        float sl = g_s[n*32 + lane];
        float at[4] = {attr[n*4+0], attr[n*4+1], attr[n*4+2], attr[n*4+3]};
        float acc = 0.f;
        for (int u = 0; u < 32; u++) {
            float su = __shfl_sync(0xffffffffu, sl, u);
            int base = u*64 + w;
#pragma unroll
            for (int a = 0; a < 4; a++) acc += su*at[a]*shW[base + a*16];
        }
        if (lane < 16) {
            int g = batch[n];
            atomicAdd(&pool[g*16 + w], acc * NORM128 * poolscale);
        }
    }
    __syncthreads();
    if (threadIdx.x < 128) atomicAdd(&out[threadIdx.x], pool[threadIdx.x]);
}

// ---------------- launcher ----------------
extern "C" void kernel_launch(void* const* d_in, const int* in_sizes, int n_in,
                              void* d_out, int out_size) {
    const float* x    = (const float*)d_in[0];
    const float* attr = (const float*)d_in[1];
    const float* evec = (const float*)d_in[2];
    const int*   batch= (const int*)  d_in[3];
    const int*   esrc = (const int*)  d_in[4];
    const int*   edst = (const int*)  d_in[5];
    const float* Wsc0 = (const float*)d_in[6];
    const float* Wsc1 = (const float*)d_in[7];
    const float* Wl10 = (const float*)d_in[8];
    const float* Wl11 = (const float*)d_in[9];
    const float* Wfc1 = (const float*)d_in[10];
    const float* Wfc2 = (const float*)d_in[11];
    const float* Wl20 = (const float*)d_in[12];
    const float* Wl21 = (const float*)d_in[13];
    const float* Wread= (const float*)d_in[14];
    int N = in_sizes[0] / 128;
    int E = in_sizes[4];

    cudaFuncSetAttribute(k_fusedA, cudaFuncAttributeMaxDynamicSharedMemorySize, FUSED_SMEM);
    cudaFuncSetAttribute(k_fusedC, cudaFuncAttributeMaxDynamicSharedMemorySize, FUSED_SMEM);
    cudaFuncSetAttribute(k_fctp1,  cudaFuncAttributeMaxDynamicSharedMemorySize, 65536);
    cudaFuncSetAttribute(k_fctp2,  cudaFuncAttributeMaxDynamicSharedMemorySize, 65536);

    // CSR build (by dst) + permuted precompute
    k_zero_deg<<<(N + 255) / 256, 256>>>(N);
    k_hist<<<(E + 255) / 256, 256>>>(edst, E);
    k_scan<<<1, SCAN_T>>>(N);
    k_fill<<<(E + 255) / 256, 256>>>(esrc, edst, E);
    k_pre_edges<<<(E + 255) / 256, 256>>>(evec, E);
    k_pre_nodes<<<(N*32 + 255) / 256, 256>>>(x, N);

    int nWG = (E + WG_TE - 1) / WG_TE;
    int nFC = 444;
    int nGB = (N + 1) / 2;

    // layer 0 + overlapped wgemm(L1)
    k_fusedA<<<nWG + nFC, 256, FUSED_SMEM>>>(attr, Wsc0, Wsc1, Wl10, Wl11,
                                             Wfc1, Wfc2, N, E, nWG, nFC);
    k_gather0<<<nGB, 256>>>(N);
    k_fusedC<<<nWG + nFC, 256, FUSED_SMEM>>>(attr, Wl20, Wl21,
                                             Wfc1 + 640, Wfc2 + 8192, N, E, nWG, nFC);
    // layer 1 (wgemm already done -> wb1)
    k_fctp1<<<444, 256, 65536>>>(attr, Wsc0 + 4096, Wsc1 + 4096,
                                 Wl10 + 4096, Wl11 + 4096, N);
    k_gather1<<<nGB, 256>>>(N);
    k_fctp2<<<444, 256, 65536>>>(attr, Wl20 + 8192, Wl21 + 8192, N);

    k_zero_out<<<1, 128>>>((float*)d_out);
    float poolscale = 1.0f / sqrtf((float)N / 8.0f);
    k_read<<<592, 128>>>(attr, batch, Wread, (float*)d_out, N, poolscale);
}